// round 8
// baseline (speedup 1.0000x reference)
#include <cuda_runtime.h>

// NeRF fine sampling + merge. FOUR rays per warp (8 lanes x 16 elements each).
#define SC   64
#define SF   128
#define NOUT 192
#define WPB  4
#define FULL 0xffffffffu

__device__ __forceinline__ void ce(float& x, float& y, bool asc) {
    float lo = fminf(x, y), hi = fmaxf(x, y);
    x = asc ? lo : hi;
    y = asc ? hi : lo;
}

// bitonic merge of 16 in-lane elements, direction a
#define MERGE16(a) do{ \
    ce(k[0],k[8],a);  ce(k[1],k[9],a);  ce(k[2],k[10],a); ce(k[3],k[11],a); \
    ce(k[4],k[12],a); ce(k[5],k[13],a); ce(k[6],k[14],a); ce(k[7],k[15],a); \
    ce(k[0],k[4],a);  ce(k[1],k[5],a);  ce(k[2],k[6],a);  ce(k[3],k[7],a);  \
    ce(k[8],k[12],a); ce(k[9],k[13],a); ce(k[10],k[14],a);ce(k[11],k[15],a);\
    ce(k[0],k[2],a);  ce(k[1],k[3],a);  ce(k[4],k[6],a);  ce(k[5],k[7],a);  \
    ce(k[8],k[10],a); ce(k[9],k[11],a); ce(k[12],k[14],a);ce(k[13],k[15],a);\
    ce(k[0],k[1],a);  ce(k[2],k[3],a);  ce(k[4],k[5],a);  ce(k[6],k[7],a);  \
    ce(k[8],k[9],a);  ce(k[10],k[11],a);ce(k[12],k[13],a);ce(k[14],k[15],a);\
}while(0)

#define XPASS(L, dmcond) do{ \
    bool dm_ = (dmcond); \
    _Pragma("unroll") \
    for (int m_ = 0; m_ < 16; m_++) { \
        float p_ = __shfl_xor_sync(FULL, k[m_], (L)); \
        k[m_] = dm_ ? fminf(k[m_], p_) : fmaxf(k[m_], p_); \
    } \
}while(0)

__global__ __launch_bounds__(32 * WPB, 6)
void fine_sample_kernel(const float* __restrict__ dists,
                        const float* __restrict__ weights,
                        const float* __restrict__ rands,
                        float* __restrict__ out, int B)
{
    __shared__ __align__(16) float  cdfs_s[WPB][4][68];
    __shared__ __align__(16) float2 pair_s[WPB][4][66];
    __shared__ __align__(16) int    pref_s[WPB][4][64];
    __shared__ __align__(16) float  out_s[WPB][4][NOUT];

    const int wid  = threadIdx.x >> 5;
    const int lane = threadIdx.x & 31;
    const int r    = lane >> 3;          // ray within warp
    const int hl   = lane & 7;           // lane within ray
    const int base = (blockIdx.x * WPB + wid) * 4;
    const int ray  = base + r;
    if (base >= B) return;

    float*  cdfs = cdfs_s[wid][r];
    float2* pair = pair_s[wid][r];
    int*    pref = pref_s[wid][r];
    float*  obf  = out_s[wid][r];

    // pref default 128
    ((int4*)pref)[2 * hl]     = make_int4(128, 128, 128, 128);
    ((int4*)pref)[2 * hl + 1] = make_int4(128, 128, 128, 128);

    // ---- dists d[8hl..8hl+7] ----
    const float4* dp4 = (const float4*)(dists + (size_t)ray * SC);
    float4 dLo = dp4[2 * hl], dHi = dp4[2 * hl + 1];
    float dd[8] = {dLo.x, dLo.y, dLo.z, dLo.w, dHi.x, dHi.y, dHi.z, dHi.w};

    // ---- weights + in-lane prefix ----
    const float* wptr = weights + (size_t)ray * (SC - 1);
    const int wi = 8 * hl;
    float p[8];
    {
        float acc = 0.0f;
        #pragma unroll
        for (int t = 0; t < 8; t++) {
            float w = (wi + t < 63) ? (wptr[wi + t] + 0.01f) : 0.0f;
            acc += w;
            p[t] = acc;
        }
    }
    float e = p[7];
    float E = e;
    #pragma unroll
    for (int off = 1; off < 8; off <<= 1) {
        float t = __shfl_up_sync(FULL, E, off);
        if (hl >= off) E += t;
    }
    float total = __shfl_sync(FULL, E, lane | 7);
    float inv = 1.0f / total;
    float Epre = E - e;

    float v[8];
    v[0] = Epre * inv;
    #pragma unroll
    for (int t = 1; t < 8; t++) v[t] = (Epre + p[t - 1]) * inv;
    ((float4*)(cdfs + wi))[0] = make_float4(v[0], v[1], v[2], v[3]);
    ((float4*)(cdfs + wi))[1] = make_float4(v[4], v[5], v[6], v[7]);

    // pair[8hl+t] = (cdf, d)
    #pragma unroll
    for (int t = 0; t < 8; t += 2)
        *((float4*)(pair + wi + t)) = make_float4(v[t], dd[t], v[t + 1], dd[t + 1]);
    if (hl == 7) pair[64] = make_float2(1.0f, dd[7]);   // sentinel

    // register probes cdf[8,16,...,56]
    const int rb = r * 8;
    float c8  = __shfl_sync(FULL, E, rb + 0) * inv;
    float c16 = __shfl_sync(FULL, E, rb + 1) * inv;
    float c24 = __shfl_sync(FULL, E, rb + 2) * inv;
    float c32 = __shfl_sync(FULL, E, rb + 3) * inv;
    float c40 = __shfl_sync(FULL, E, rb + 4) * inv;
    float c48 = __shfl_sync(FULL, E, rb + 5) * inv;
    float c56 = __shfl_sync(FULL, E, rb + 6) * inv;

    // ---- load 16 u's (element i = hl*16 + m) ----
    const float4* up4 = (const float4*)(rands + (size_t)ray * SF);
    float k[16];
    #pragma unroll
    for (int q = 0; q < 4; q++) {
        float4 u = up4[4 * hl + q];
        k[4 * q] = u.x; k[4 * q + 1] = u.y; k[4 * q + 2] = u.z; k[4 * q + 3] = u.w;
    }

    // ---- bitonic sort of 128 u's (8 lanes x 16 regs), asc = ((i&kk)==0) ----
    // kk=2
    ce(k[0],k[1],true);  ce(k[2],k[3],false); ce(k[4],k[5],true);  ce(k[6],k[7],false);
    ce(k[8],k[9],true);  ce(k[10],k[11],false);ce(k[12],k[13],true);ce(k[14],k[15],false);
    // kk=4
    ce(k[0],k[2],true);  ce(k[1],k[3],true);  ce(k[4],k[6],false); ce(k[5],k[7],false);
    ce(k[8],k[10],true); ce(k[9],k[11],true); ce(k[12],k[14],false);ce(k[13],k[15],false);
    ce(k[0],k[1],true);  ce(k[2],k[3],true);  ce(k[4],k[5],false); ce(k[6],k[7],false);
    ce(k[8],k[9],true);  ce(k[10],k[11],true);ce(k[12],k[13],false);ce(k[14],k[15],false);
    // kk=8
    ce(k[0],k[4],true);  ce(k[1],k[5],true);  ce(k[2],k[6],true);  ce(k[3],k[7],true);
    ce(k[8],k[12],false);ce(k[9],k[13],false);ce(k[10],k[14],false);ce(k[11],k[15],false);
    ce(k[0],k[2],true);  ce(k[1],k[3],true);  ce(k[4],k[6],true);  ce(k[5],k[7],true);
    ce(k[8],k[10],false);ce(k[9],k[11],false);ce(k[12],k[14],false);ce(k[13],k[15],false);
    ce(k[0],k[1],true);  ce(k[2],k[3],true);  ce(k[4],k[5],true);  ce(k[6],k[7],true);
    ce(k[8],k[9],false); ce(k[10],k[11],false);ce(k[12],k[13],false);ce(k[14],k[15],false);
    // kk=16
    { bool a = (hl & 1) == 0; MERGE16(a); }
    // kk=32
    { bool a = (hl & 2) == 0;
      XPASS(1, ((hl & 1) == 0) == a);
      MERGE16(a); }
    // kk=64
    { bool a = (hl & 4) == 0;
      XPASS(2, ((hl & 2) == 0) == a);
      XPASS(1, ((hl & 1) == 0) == a);
      MERGE16(a); }
    // kk=128 (ascending)
    XPASS(4, (hl & 4) == 0);
    XPASS(2, (hl & 2) == 0);
    XPASS(1, (hl & 1) == 0);
    MERGE16(true);
    __syncwarp();   // tables ready

    // ---- search + interp on SORTED u's; scatter; first-occurrence ----
    int prev = -1, idx0 = 0;
    #pragma unroll
    for (int m = 0; m < 16; m++) {
        float u = k[m];
        int idx = (c32 <= u) ? 32 : 0;
        float q2 = idx ? c48 : c16;
        if (q2 <= u) idx += 16;
        float q3 = (idx & 32) ? ((idx & 16) ? c56 : c40)
                              : ((idx & 16) ? c24 : c8);
        if (q3 <= u) idx += 8;
        if (cdfs[idx + 4] <= u) idx += 4;
        if (cdfs[idx + 2] <= u) idx += 2;
        if (cdfs[idx + 1] <= u) idx += 1;
        float2 P0 = pair[idx];
        float2 P1 = pair[idx + 1];
        float den = P1.x - P0.x;
        den = (den < 1e-5f) ? 1.0f : den;
        float t = (u - P0.x) / den;
        float s = fmaf(t, P1.y - P0.y, P0.y);
        s = fminf(s, P1.y);
        obf[hl * 16 + m + idx + 1] = s;          // pos = rank + bin + 1
        if (m == 0) idx0 = idx;
        else if (idx != prev) pref[idx] = hl * 16 + m;
        prev = idx;
    }
    int pb = __shfl_up_sync(FULL, prev, 1);
    if (hl == 0) pb = -1;
    if (idx0 != pb) pref[idx0] = hl * 16;
    __syncwarp();

    // ---- suffix-min over pref[0..63] (8 per lane) ----
    int4 Q0 = ((int4*)pref)[2 * hl];
    int4 Q1 = ((int4*)pref)[2 * hl + 1];
    int S = min(min(min(Q0.x, Q0.y), min(Q0.z, Q0.w)),
                min(min(Q1.x, Q1.y), min(Q1.z, Q1.w)));
    #pragma unroll
    for (int off = 1; off < 8; off <<= 1) {
        int t = __shfl_down_sync(FULL, S, off);
        if (hl + off < 8) S = min(S, t);
    }
    int Sn = __shfl_down_sync(FULL, S, 1);
    if (hl == 7) Sn = 128;
    int f7 = min(Q1.w, Sn);
    int f6 = min(Q1.z, f7);
    int f5 = min(Q1.y, f6);
    int f4 = min(Q1.x, f5);
    int f3 = min(Q0.w, f4);
    int f2 = min(Q0.z, f3);
    int f1 = min(Q0.y, f2);
    int f0 = min(Q0.x, f1);

    // ---- dists: pos = j + prefix[j] ----
    obf[wi + 0 + f0] = dd[0];
    obf[wi + 1 + f1] = dd[1];
    obf[wi + 2 + f2] = dd[2];
    obf[wi + 3 + f3] = dd[3];
    obf[wi + 4 + f4] = dd[4];
    obf[wi + 5 + f5] = dd[5];
    obf[wi + 6 + f6] = dd[6];
    obf[wi + 7 + f7] = dd[7];
    __syncwarp();

    // ---- vectorized coalesced output (4 rays contiguous) ----
    const float4* ob4 = (const float4*)out_s[wid][0];
    float4* op4 = (float4*)(out + (size_t)base * NOUT);
    #pragma unroll
    for (int t = 0; t < 6; t++)
        op4[t * 32 + lane] = ob4[t * 32 + lane];
}

extern "C" void kernel_launch(void* const* d_in, const int* in_sizes, int n_in,
                              void* d_out, int out_size) {
    const float* dists   = (const float*)d_in[0];
    const float* weights = (const float*)d_in[1];
    const float* rands   = (const float*)d_in[2];
    float* out = (float*)d_out;
    int B = in_sizes[0] / SC;
    int raysPerBlock = 4 * WPB;
    int blocks = (B + raysPerBlock - 1) / raysPerBlock;
    fine_sample_kernel<<<blocks, 32 * WPB>>>(dists, weights, rands, out, B);
}

// round 9
// speedup vs baseline: 1.1323x; 1.1323x over previous
#include <cuda_runtime.h>

// NeRF fine sampling + merge. TWO rays per warp (16 lanes x 8 elements each).
// R7 topology + fused search tail: per-sample LSU 6 -> 4.
#define SC   64
#define SF   128
#define NOUT 192
#define WPB  8
#define FULL 0xffffffffu

__device__ __forceinline__ void ce(float& x, float& y, bool asc) {
    float lo = fminf(x, y), hi = fmaxf(x, y);
    x = asc ? lo : hi;
    y = asc ? hi : lo;
}

__global__ __launch_bounds__(32 * WPB, 4)
void fine_sample_kernel(const float* __restrict__ dists,
                        const float* __restrict__ weights,
                        const float* __restrict__ rands,
                        float* __restrict__ out, int B)
{
    __shared__ __align__(16) float  cdfs_s[WPB][2][68];   // scalar cdf (L4 probes)
    __shared__ __align__(16) float4 ta_s[WPB][2][16];     // (c[4i+1..4i+4])
    __shared__ __align__(16) float2 dpair_s[WPB][2][64];  // (d[i], d[i+1])
    __shared__ __align__(16) int    pref_s[WPB][2][64];   // first-rank-per-bin
    __shared__ __align__(16) float  out_s[WPB][2][NOUT];

    const int wid  = threadIdx.x >> 5;
    const int lane = threadIdx.x & 31;
    const int half = lane >> 4;
    const int hl   = lane & 15;
    const int base = (blockIdx.x * WPB + wid) * 2;
    const int ray  = base + half;
    if (ray >= B) return;

    float*  cdfs  = cdfs_s[wid][half];
    float4* ta    = ta_s[wid][half];
    float2* dpair = dpair_s[wid][half];
    int*    pref  = pref_s[wid][half];
    float*  obf   = out_s[wid][half];

    // pref default: 128
    ((int4*)pref)[hl] = make_int4(128, 128, 128, 128);

    // ---- loads ----
    const float4* dptr4 = (const float4*)(dists + (size_t)ray * SC);
    float4 dd = dptr4[hl];                               // d[4hl..4hl+3]
    const float* wptr = weights + (size_t)ray * (SC - 1);
    const int wi = 4 * hl;
    float w0 = wptr[wi]     + 0.01f;
    float w1 = wptr[wi + 1] + 0.01f;
    float w2 = wptr[wi + 2] + 0.01f;
    float w3 = (hl < 15) ? (wptr[wi + 3] + 0.01f) : 0.0f;

    // ---- scan (width 16, both rays in parallel) ----
    float p1 = w0, p2 = p1 + w1, p3 = p2 + w2;
    float e  = p3 + w3;
    float E = e;
    #pragma unroll
    for (int off = 1; off < 16; off <<= 1) {
        float t = __shfl_up_sync(FULL, E, off);
        if (hl >= off) E += t;
    }
    const int hb = half << 4;
    float total = __shfl_sync(FULL, E, hb | 15);
    float inv = 1.0f / total;
    float c0e = E - e;
    float4 cv = make_float4(c0e * inv, (c0e + p1) * inv,
                            (c0e + p2) * inv, (c0e + p3) * inv);  // cdf[4hl..4hl+3]
    float ctop = E * inv;                                // cdf[4hl+4]; hl=15 -> 1.0 sentinel
    ((float4*)cdfs)[hl] = cv;
    ta[hl] = make_float4(cv.y, cv.z, cv.w, ctop);

    // register probes cdf[8|16|24|32|40|48|56]
    float c8  = __shfl_sync(FULL, E, hb | 1)  * inv;
    float c16 = __shfl_sync(FULL, E, hb | 3)  * inv;
    float c24 = __shfl_sync(FULL, E, hb | 5)  * inv;
    float c32 = __shfl_sync(FULL, E, hb | 7)  * inv;
    float c40 = __shfl_sync(FULL, E, hb | 9)  * inv;
    float c48 = __shfl_sync(FULL, E, hb | 11) * inv;
    float c56 = __shfl_sync(FULL, E, hb | 13) * inv;

    // ---- dpair table: (d[i], d[i+1]) ----
    float dnext = __shfl_down_sync(FULL, dd.x, 1);
    if (hl == 15) dnext = dd.w;                          // d[64] := d[63]
    ((float4*)(dpair + wi))[0] = make_float4(dd.x, dd.y, dd.y, dd.z);
    ((float4*)(dpair + wi))[1] = make_float4(dd.z, dd.w, dd.w, dnext);

    // ---- load 8 u's (element index i = hl*8 + m) ----
    const float4* up4 = (const float4*)(rands + (size_t)ray * SF);
    float4 ua = up4[2 * hl], ub = up4[2 * hl + 1];
    float k[8] = {ua.x, ua.y, ua.z, ua.w, ub.x, ub.y, ub.z, ub.w};

    // ---- bitonic sort of 128 u's across 16 lanes x 8 regs ----
    ce(k[0], k[1], true);  ce(k[2], k[3], false);
    ce(k[4], k[5], true);  ce(k[6], k[7], false);
    ce(k[0], k[2], true);  ce(k[1], k[3], true);
    ce(k[0], k[1], true);  ce(k[2], k[3], true);
    ce(k[4], k[6], false); ce(k[5], k[7], false);
    ce(k[4], k[5], false); ce(k[6], k[7], false);
    {
        bool a = (hl & 1) == 0;
        ce(k[0], k[4], a); ce(k[1], k[5], a); ce(k[2], k[6], a); ce(k[3], k[7], a);
        ce(k[0], k[2], a); ce(k[1], k[3], a); ce(k[4], k[6], a); ce(k[5], k[7], a);
        ce(k[0], k[1], a); ce(k[2], k[3], a); ce(k[4], k[5], a); ce(k[6], k[7], a);
    }
    #pragma unroll
    for (int kk = 16; kk <= 128; kk <<= 1) {
        bool a = (hl & (kk >> 3)) == 0;
        #pragma unroll
        for (int L = kk >> 4; L >= 1; L >>= 1) {
            bool dm = (((hl & L) == 0) == a);
            #pragma unroll
            for (int m = 0; m < 8; m++) {
                float p = __shfl_xor_sync(FULL, k[m], L);
                k[m] = dm ? fminf(k[m], p) : fmaxf(k[m], p);
            }
        }
        ce(k[0], k[4], a); ce(k[1], k[5], a); ce(k[2], k[6], a); ce(k[3], k[7], a);
        ce(k[0], k[2], a); ce(k[1], k[3], a); ce(k[4], k[6], a); ce(k[5], k[7], a);
        ce(k[0], k[1], a); ce(k[2], k[3], a); ce(k[4], k[5], a); ce(k[6], k[7], a);
    }
    __syncwarp();   // tables ready

    // ---- search + interp on SORTED u's; scatter; first-occurrence ----
    int prev = -1, idx0 = 0;
    #pragma unroll
    for (int m = 0; m < 8; m++) {
        float u = k[m];
        int idx = 0; float cb = 0.0f;
        if (c32 <= u) { idx = 32; cb = c32; }
        float q2 = idx ? c48 : c16;
        if (q2 <= u) { idx += 16; cb = q2; }
        float q3 = (idx & 32) ? ((idx & 16) ? c56 : c40)
                              : ((idx & 16) ? c24 : c8);
        if (q3 <= u) { idx += 8; cb = q3; }
        float p4 = cdfs[idx + 4];
        if (p4 <= u) { idx += 4; cb = p4; }
        float4 T = ta[idx >> 2];      // (c[idx+1], c[idx+2], c[idx+3], c[idx+4])
        int o = 0;
        if (T.y <= u) { o = 2; cb = T.y; }
        float cn = o ? T.z : T.x;
        if (cn <= u) { o += 1; cb = cn; }
        float c1 = (o & 1) ? ((o & 2) ? T.w : T.y)
                           : ((o & 2) ? T.z : T.x);
        idx += o;
        float2 dp = dpair[idx];       // (d[idx], d[idx+1])
        float den = c1 - cb;
        den = (den < 1e-5f) ? 1.0f : den;
        float t = (u - cb) / den;
        float s = fmaf(t, dp.y - dp.x, dp.x);
        s = fminf(s, dp.y);
        obf[hl * 8 + m + idx + 1] = s;          // pos = rank + bin + 1
        if (m == 0) idx0 = idx;
        else if (idx != prev) pref[idx] = hl * 8 + m;
        prev = idx;
    }
    int pb = __shfl_up_sync(FULL, prev, 1);
    if (hl == 0) pb = -1;
    if (idx0 != pb) pref[idx0] = hl * 8;
    __syncwarp();

    // ---- suffix-min over pref[0..63] (4 per lane) ----
    int4 P = ((int4*)pref)[hl];
    int s3 = P.w;
    int s2 = min(P.z, s3);
    int s1 = min(P.y, s2);
    int s0 = min(P.x, s1);
    int S = s0;
    #pragma unroll
    for (int off = 1; off < 16; off <<= 1) {
        int t = __shfl_down_sync(FULL, S, off);
        if (hl + off < 16) S = min(S, t);
    }
    int Sn = __shfl_down_sync(FULL, S, 1);
    if (hl == 15) Sn = 128;
    int f3 = min(s3, Sn);
    int f2 = min(s2, f3);
    int f1 = min(s1, f2);
    int f0 = min(s0, f1);

    // ---- dists: pos = j + prefix[j] ----
    obf[wi     + f0] = dd.x;
    obf[wi + 1 + f1] = dd.y;
    obf[wi + 2 + f2] = dd.z;
    obf[wi + 3 + f3] = dd.w;
    __syncwarp();

    // ---- vectorized coalesced output (both rays contiguous) ----
    const float4* ob4 = (const float4*)out_s[wid][0];
    float4* op4 = (float4*)(out + (size_t)base * NOUT);
    #pragma unroll
    for (int t = 0; t < 3; t++)
        op4[t * 32 + lane] = ob4[t * 32 + lane];
}

extern "C" void kernel_launch(void* const* d_in, const int* in_sizes, int n_in,
                              void* d_out, int out_size) {
    const float* dists   = (const float*)d_in[0];
    const float* weights = (const float*)d_in[1];
    const float* rands   = (const float*)d_in[2];
    float* out = (float*)d_out;
    int B = in_sizes[0] / SC;
    int raysPerBlock = 2 * WPB;
    int blocks = (B + raysPerBlock - 1) / raysPerBlock;
    fine_sample_kernel<<<blocks, 32 * WPB>>>(dists, weights, rands, out, B);
}

// round 10
// speedup vs baseline: 1.1644x; 1.0283x over previous
#include <cuda_runtime.h>

// NeRF fine sampling + merge. TWO rays per warp (16 lanes x 8 elements each).
// R9 fused search tail + register-diet for occupancy.
#define SC   64
#define SF   128
#define NOUT 192
#define WPB  8
#define FULL 0xffffffffu

// per-(warp,half) smem blob layout (float offsets)
#define TA_OFF    0     // float4[16]: (c[4i+1..4i+4])
#define DP_OFF    64    // float2[64]: (d[i], d[i+1])
#define CDF_OFF   192   // float[68]:  cdf[0..63] (scalar probes)
#define PREF_OFF  260   // int[64]:    first-rank-per-bin
#define BLOB_SZ   328   // padded

__device__ __forceinline__ void ce(float& x, float& y, bool asc) {
    float lo = fminf(x, y), hi = fmaxf(x, y);
    x = asc ? lo : hi;
    y = asc ? hi : lo;
}

__global__ __launch_bounds__(32 * WPB, 5)
void fine_sample_kernel(const float* __restrict__ dists,
                        const float* __restrict__ weights,
                        const float* __restrict__ rands,
                        float* __restrict__ out, int B)
{
    __shared__ __align__(16) float blob_s[WPB][2][BLOB_SZ];
    __shared__ __align__(16) float out_s[WPB][2][NOUT];

    const int wid  = threadIdx.x >> 5;
    const int lane = threadIdx.x & 31;
    const int half = lane >> 4;
    const int hl   = lane & 15;
    const int base = (blockIdx.x * WPB + wid) * 2;
    if (base >= B) return;
    const int ray  = base + half;

    float* blob = blob_s[wid][half];
    float* obf  = out_s[wid][half];
    float4* ta    = (float4*)(blob + TA_OFF);
    float2* dpair = (float2*)(blob + DP_OFF);
    float*  cdfs  = blob + CDF_OFF;
    int*    pref  = (int*)(blob + PREF_OFF);

    // pref default: 128
    ((int4*)pref)[hl] = make_int4(128, 128, 128, 128);

    const int wi = 4 * hl;
    {
        // ---- loads ----
        const float4* dptr4 = (const float4*)(dists + (size_t)ray * SC);
        float4 dd = dptr4[hl];                               // d[4hl..4hl+3]
        const float* wptr = weights + (size_t)ray * (SC - 1);
        float w0 = wptr[wi]     + 0.01f;
        float w1 = wptr[wi + 1] + 0.01f;
        float w2 = wptr[wi + 2] + 0.01f;
        float w3 = (hl < 15) ? (wptr[wi + 3] + 0.01f) : 0.0f;

        // ---- scan (width 16, both rays in parallel) ----
        float p1 = w0, p2 = p1 + w1, p3 = p2 + w2;
        float e  = p3 + w3;
        float E = e;
        #pragma unroll
        for (int off = 1; off < 16; off <<= 1) {
            float t = __shfl_up_sync(FULL, E, off);
            if (hl >= off) E += t;
        }
        float total = __shfl_sync(FULL, E, lane | 15);
        float inv = 1.0f / total;
        float c0e = E - e;
        float4 cv = make_float4(c0e * inv, (c0e + p1) * inv,
                                (c0e + p2) * inv, (c0e + p3) * inv);
        float ctop = E * inv;                                // cdf[4hl+4]; hl=15 -> 1.0
        ((float4*)cdfs)[hl] = cv;
        ta[hl] = make_float4(cv.y, cv.z, cv.w, ctop);

        // ---- dpair table: (d[i], d[i+1]) ----
        float dnext = __shfl_down_sync(FULL, dd.x, 1);
        if (hl == 15) dnext = dd.w;                          // d[64] := d[63]
        ((float4*)(dpair + wi))[0] = make_float4(dd.x, dd.y, dd.y, dd.z);
        ((float4*)(dpair + wi))[1] = make_float4(dd.z, dd.w, dd.w, dnext);
    }

    // ---- load 8 u's (element index i = hl*8 + m) ----
    float k[8];
    {
        const float4* up4 = (const float4*)(rands + (size_t)ray * SF);
        float4 ua = up4[2 * hl], ub = up4[2 * hl + 1];
        k[0]=ua.x; k[1]=ua.y; k[2]=ua.z; k[3]=ua.w;
        k[4]=ub.x; k[5]=ub.y; k[6]=ub.z; k[7]=ub.w;
    }

    // ---- bitonic sort of 128 u's across 16 lanes x 8 regs ----
    ce(k[0], k[1], true);  ce(k[2], k[3], false);
    ce(k[4], k[5], true);  ce(k[6], k[7], false);
    ce(k[0], k[2], true);  ce(k[1], k[3], true);
    ce(k[0], k[1], true);  ce(k[2], k[3], true);
    ce(k[4], k[6], false); ce(k[5], k[7], false);
    ce(k[4], k[5], false); ce(k[6], k[7], false);
    {
        bool a = (hl & 1) == 0;
        ce(k[0], k[4], a); ce(k[1], k[5], a); ce(k[2], k[6], a); ce(k[3], k[7], a);
        ce(k[0], k[2], a); ce(k[1], k[3], a); ce(k[4], k[6], a); ce(k[5], k[7], a);
        ce(k[0], k[1], a); ce(k[2], k[3], a); ce(k[4], k[5], a); ce(k[6], k[7], a);
    }
    #pragma unroll
    for (int kk = 16; kk <= 128; kk <<= 1) {
        bool a = (hl & (kk >> 3)) == 0;
        #pragma unroll
        for (int L = kk >> 4; L >= 1; L >>= 1) {
            bool dm = (((hl & L) == 0) == a);
            #pragma unroll
            for (int m = 0; m < 8; m++) {
                float p = __shfl_xor_sync(FULL, k[m], L);
                k[m] = dm ? fminf(k[m], p) : fmaxf(k[m], p);
            }
        }
        ce(k[0], k[4], a); ce(k[1], k[5], a); ce(k[2], k[6], a); ce(k[3], k[7], a);
        ce(k[0], k[2], a); ce(k[1], k[3], a); ce(k[4], k[6], a); ce(k[5], k[7], a);
        ce(k[0], k[1], a); ce(k[2], k[3], a); ce(k[4], k[5], a); ce(k[6], k[7], a);
    }
    __syncwarp();   // tables ready

    // ---- reload probes (broadcast LDS, frees regs through the sort) ----
    float c8  = cdfs[8],  c16 = cdfs[16], c24 = cdfs[24], c32 = cdfs[32];
    float c40 = cdfs[40], c48 = cdfs[48], c56 = cdfs[56];

    // ---- search + interp on SORTED u's; scatter; first-occurrence ----
    int prev = -1, idx0 = 0;
    #pragma unroll
    for (int m = 0; m < 8; m++) {
        float u = k[m];
        int idx = 0; float cb = 0.0f;
        if (c32 <= u) { idx = 32; cb = c32; }
        float q2 = idx ? c48 : c16;
        if (q2 <= u) { idx += 16; cb = q2; }
        float q3 = (idx & 32) ? ((idx & 16) ? c56 : c40)
                              : ((idx & 16) ? c24 : c8);
        if (q3 <= u) { idx += 8; cb = q3; }
        float p4 = cdfs[idx + 4];
        if (p4 <= u) { idx += 4; cb = p4; }
        float4 T = ta[idx >> 2];      // (c[idx+1..idx+4])
        int o = 0;
        if (T.y <= u) { o = 2; cb = T.y; }
        float cn = o ? T.z : T.x;
        if (cn <= u) { o += 1; cb = cn; }
        float c1 = (o & 1) ? ((o & 2) ? T.w : T.y)
                           : ((o & 2) ? T.z : T.x);
        idx += o;
        float2 dp = dpair[idx];       // (d[idx], d[idx+1])
        float den = c1 - cb;
        den = (den < 1e-5f) ? 1.0f : den;
        float t = (u - cb) / den;
        float s = fmaf(t, dp.y - dp.x, dp.x);
        s = fminf(s, dp.y);
        obf[hl * 8 + m + idx + 1] = s;          // pos = rank + bin + 1
        if (m == 0) idx0 = idx;
        else if (idx != prev) pref[idx] = hl * 8 + m;
        prev = idx;
    }
    int pb = __shfl_up_sync(FULL, prev, 1);
    if (hl == 0) pb = -1;
    if (idx0 != pb) pref[idx0] = hl * 8;
    __syncwarp();

    // ---- suffix-min over pref[0..63] (4 per lane) ----
    int4 P = ((int4*)pref)[hl];
    int s3 = P.w;
    int s2 = min(P.z, s3);
    int s1 = min(P.y, s2);
    int s0 = min(P.x, s1);
    int S = s0;
    #pragma unroll
    for (int off = 1; off < 16; off <<= 1) {
        int t = __shfl_down_sync(FULL, S, off);
        if (hl + off < 16) S = min(S, t);
    }
    int Sn = __shfl_down_sync(FULL, S, 1);
    if (hl == 15) Sn = 128;
    int f3 = min(s3, Sn);
    int f2 = min(s2, f3);
    int f1 = min(s1, f2);
    int f0 = min(s0, f1);

    // ---- dists reloaded from dpair; pos = j + prefix[j] ----
    float4 g0 = ((float4*)(dpair + wi))[0];     // (d0, d1, d1, d2)
    float4 g1 = ((float4*)(dpair + wi))[1];     // (d2, d3, d3, d4)
    obf[wi     + f0] = g0.x;
    obf[wi + 1 + f1] = g0.z;
    obf[wi + 2 + f2] = g1.x;
    obf[wi + 3 + f3] = g1.z;
    __syncwarp();

    // ---- vectorized coalesced output (both rays contiguous) ----
    const float4* ob4 = (const float4*)out_s[wid][0];
    float4* op4 = (float4*)(out + (size_t)base * NOUT);
    #pragma unroll
    for (int t = 0; t < 3; t++)
        op4[t * 32 + lane] = ob4[t * 32 + lane];
}

extern "C" void kernel_launch(void* const* d_in, const int* in_sizes, int n_in,
                              void* d_out, int out_size) {
    const float* dists   = (const float*)d_in[0];
    const float* weights = (const float*)d_in[1];
    const float* rands   = (const float*)d_in[2];
    float* out = (float*)d_out;
    int B = in_sizes[0] / SC;
    int raysPerBlock = 2 * WPB;
    int blocks = (B + raysPerBlock - 1) / raysPerBlock;
    fine_sample_kernel<<<blocks, 32 * WPB>>>(dists, weights, rands, out, B);
}